// round 3
// baseline (speedup 1.0000x reference)
#include <cuda_runtime.h>
#include <cuda_bf16.h>
#include <math.h>

#define SQ 2048
#define BB 32
#define DD 256
#define HH 4
#define NN (SQ*BB)
#define EPSV 1e-5f

// ---------------- scratch (device globals; allocation-free rule) -----------
__device__ __align__(128) float g_W [NN*DD];
__device__ __align__(128) float g_W2[NN*DD];
__device__ __align__(128) float g_W4[NN*DD];
__device__ __align__(128) float g_Vi[NN*DD];
__device__ __align__(128) float g_Mq[HH*DD*DD];
__device__ __align__(128) float g_Mk[HH*DD*DD];
__device__ __align__(128) float g_Mv[HH*DD*DD];
__device__ float g_cq[HH*DD], g_ck[HH*DD], g_cv[HH*DD], g_cw[HH*DD];
__device__ float g_ps[512*DD], g_pq2[512*DD];
__device__ float g_sc1[DD], g_sh1[DD], g_sc2[DD], g_sh2[DD];
__device__ float g_pm[BB*16*DD], g_pd[BB*16*DD], g_pw[BB*16*DD];
__device__ float g_x[BB*HH*DD];
__device__ float g_h0[BB*DD], g_h1[BB*DD];

// ---------------- helpers ---------------------------------------------------
__device__ __forceinline__ unsigned split_pack(float f0, float f1, unsigned& lo) {
    __nv_bfloat16 h0 = __float2bfloat16(f0);
    __nv_bfloat16 h1 = __float2bfloat16(f1);
    __nv_bfloat16 l0 = __float2bfloat16(f0 - __bfloat162float(h0));
    __nv_bfloat16 l1 = __float2bfloat16(f1 - __bfloat162float(h1));
    __nv_bfloat162 hv = __halves2bfloat162(h0, h1);   // .x = low half = even k
    __nv_bfloat162 lv = __halves2bfloat162(l0, l1);
    lo = *reinterpret_cast<unsigned*>(&lv);
    return *reinterpret_cast<unsigned*>(&hv);
}

__device__ __forceinline__ void mma16816(float* c, const unsigned* a, const unsigned* b) {
    asm volatile(
        "mma.sync.aligned.m16n8k16.row.col.f32.bf16.bf16.f32 "
        "{%0,%1,%2,%3}, {%4,%5,%6,%7}, {%8,%9}, {%0,%1,%2,%3};"
        : "+f"(c[0]), "+f"(c[1]), "+f"(c[2]), "+f"(c[3])
        : "r"(a[0]), "r"(a[1]), "r"(a[2]), "r"(a[3]), "r"(b[0]), "r"(b[1]));
}

// ---------------- main GEMM: C = [A0|A1] @ [B0|sgn*B1]^T + bias -------------
// A rows: lda=256 for both segments (K split at 256). Optional per-channel
// pre-transform on A: relu(a*ascale[ch]+ashift[ch]). Tile 128x64, BK=32.
__global__ __launch_bounds__(256, 2)
void gemm_bf16x3(const float* __restrict__ A0, const float* __restrict__ A1,
                 const float* __restrict__ B0, const float* __restrict__ B1,
                 float b1sign, const float* __restrict__ bias,
                 const float* __restrict__ ascale, const float* __restrict__ ashift,
                 float* __restrict__ C, int Ktot)
{
    __shared__ unsigned AsH[128][20], AsL[128][20];
    __shared__ unsigned BsH[64][20],  BsL[64][20];
    const int tid = threadIdx.x, warp = tid >> 5, lane = tid & 31;
    const int wm = warp & 3, wn = warp >> 2;
    const int g = lane >> 2, tg = lane & 3;
    const int rowBlk = blockIdx.y * 128, colBlk = blockIdx.x * 64;

    float acc[2][4][4];
#pragma unroll
    for (int a = 0; a < 2; ++a)
#pragma unroll
        for (int b = 0; b < 4; ++b)
#pragma unroll
            for (int c = 0; c < 4; ++c) acc[a][b][c] = 0.f;

    const int nK = Ktot >> 5;
    for (int kt = 0; kt < nK; ++kt) {
        const int k0 = kt * 32;
        const float* asrc = A0; int kb = k0;
        if (k0 >= DD && A1) { asrc = A1; kb = k0 - DD; }
#pragma unroll
        for (int p = 0; p < 4; ++p) {
            int idx = tid + p * 256, r = idx >> 3, c4 = (idx & 7) * 4;
            float4 v = *reinterpret_cast<const float4*>(&asrc[(size_t)(rowBlk + r) * DD + kb + c4]);
            float f[4] = {v.x, v.y, v.z, v.w};
            if (ascale) {
#pragma unroll
                for (int j = 0; j < 4; ++j) {
                    int ch = kb + c4 + j;
                    f[j] = fmaxf(f[j] * ascale[ch] + ashift[ch], 0.f);
                }
            }
            unsigned l0, l1;
            unsigned h0 = split_pack(f[0], f[1], l0);
            unsigned h1 = split_pack(f[2], f[3], l1);
            int pc = c4 >> 1;
            AsH[r][pc] = h0; AsH[r][pc + 1] = h1;
            AsL[r][pc] = l0; AsL[r][pc + 1] = l1;
        }
        const float* bsrc = B0; float sgn = 1.f; int kb2 = k0;
        if (k0 >= DD && B1) { bsrc = B1; sgn = b1sign; kb2 = k0 - DD; }
#pragma unroll
        for (int p = 0; p < 2; ++p) {
            int idx = tid + p * 256, r = idx >> 3, c4 = (idx & 7) * 4;
            float4 v = *reinterpret_cast<const float4*>(&bsrc[(size_t)(colBlk + r) * DD + kb2 + c4]);
            float f[4] = {v.x * sgn, v.y * sgn, v.z * sgn, v.w * sgn};
            unsigned l0, l1;
            unsigned h0 = split_pack(f[0], f[1], l0);
            unsigned h1 = split_pack(f[2], f[3], l1);
            int pc = c4 >> 1;
            BsH[r][pc] = h0; BsH[r][pc + 1] = h1;
            BsL[r][pc] = l0; BsL[r][pc + 1] = l1;
        }
        __syncthreads();
#pragma unroll
        for (int kk = 0; kk < 2; ++kk) {
            const int kp = kk * 8;
            unsigned aH[2][4], aL[2][4], bH[4][2], bL[4][2];
#pragma unroll
            for (int mi = 0; mi < 2; ++mi) {
                int r0 = wm * 32 + mi * 16 + g;
                aH[mi][0] = AsH[r0][kp + tg];     aH[mi][1] = AsH[r0 + 8][kp + tg];
                aH[mi][2] = AsH[r0][kp + tg + 4]; aH[mi][3] = AsH[r0 + 8][kp + tg + 4];
                aL[mi][0] = AsL[r0][kp + tg];     aL[mi][1] = AsL[r0 + 8][kp + tg];
                aL[mi][2] = AsL[r0][kp + tg + 4]; aL[mi][3] = AsL[r0 + 8][kp + tg + 4];
            }
#pragma unroll
            for (int ni = 0; ni < 4; ++ni) {
                int c0 = wn * 32 + ni * 8 + g;
                bH[ni][0] = BsH[c0][kp + tg]; bH[ni][1] = BsH[c0][kp + tg + 4];
                bL[ni][0] = BsL[c0][kp + tg]; bL[ni][1] = BsL[c0][kp + tg + 4];
            }
#pragma unroll
            for (int mi = 0; mi < 2; ++mi)
#pragma unroll
                for (int ni = 0; ni < 4; ++ni) {
                    mma16816(acc[mi][ni], aH[mi], bH[ni]);
                    mma16816(acc[mi][ni], aH[mi], bL[ni]);
                    mma16816(acc[mi][ni], aL[mi], bH[ni]);
                }
        }
        __syncthreads();
    }
#pragma unroll
    for (int mi = 0; mi < 2; ++mi)
#pragma unroll
        for (int ni = 0; ni < 4; ++ni) {
            int r = rowBlk + wm * 32 + mi * 16 + g;
            int c = colBlk + wn * 32 + ni * 8 + tg * 2;
            float b0 = bias[c], b1v = bias[c + 1];
            C[(size_t)r * DD + c]         = acc[mi][ni][0] + b0;
            C[(size_t)r * DD + c + 1]     = acc[mi][ni][1] + b1v;
            C[(size_t)(r + 8) * DD + c]   = acc[mi][ni][2] + b0;
            C[(size_t)(r + 8) * DD + c + 1] = acc[mi][ni][3] + b1v;
        }
}

// ---------------- BN stats (deterministic 2-stage) --------------------------
__global__ void bn_stats1(const float* __restrict__ X) {
    int d = threadIdx.x, blk = blockIdx.x;                 // 512 blocks x 128 rows
    const float* p = X + (size_t)blk * 128 * DD + d;
    float s = 0.f, q = 0.f;
#pragma unroll 4
    for (int r = 0; r < 128; ++r) { float x = p[(size_t)r * DD]; s += x; q += x * x; }
    g_ps[blk * DD + d] = s; g_pq2[blk * DD + d] = q;
}

__global__ void bn_stats2(const float* __restrict__ gamma, const float* __restrict__ beta,
                          float* __restrict__ sc, float* __restrict__ sh) {
    int d = blockIdx.x, t = threadIdx.x;                   // 256 blocks (channel)
    float s  = g_ps [t * DD + d] + g_ps [(t + 256) * DD + d];
    float qq = g_pq2[t * DD + d] + g_pq2[(t + 256) * DD + d];
    __shared__ float ss[256], sq[256];
    ss[t] = s; sq[t] = qq; __syncthreads();
    for (int o = 128; o > 0; o >>= 1) {
        if (t < o) { ss[t] += ss[t + o]; sq[t] += sq[t + o]; }
        __syncthreads();
    }
    if (t == 0) {
        float mean = ss[0] / (float)NN;
        float var  = sq[0] / (float)NN - mean * mean;
        float is   = rsqrtf(fmaxf(var, 0.f) + EPSV);
        float scale = gamma[d] * is;
        sc[d] = scale; sh[d] = beta[d] - mean * scale;
    }
}

// ---------------- online softmax over S fused with weighted-V sum -----------
__global__ void smax_part(const float* __restrict__ W4, const float* __restrict__ V) {
    int d = threadIdx.x, ch = blockIdx.x, b = blockIdx.y;  // 16 S-chunks x 32 b
    size_t base = ((size_t)ch * 128 * BB + b) * DD + d;
    float m = -1e30f, den = 0.f, wv = 0.f;
#pragma unroll 2
    for (int s = 0; s < 128; ++s) {
        size_t o = base + (size_t)s * BB * DD;
        float w = W4[o], vv = V[o];
        float nm = fmaxf(m, w);
        float f = __expf(m - nm), e = __expf(w - nm);
        den = den * f + e; wv = wv * f + e * vv; m = nm;
    }
    int o = (b * 16 + ch) * DD + d;
    g_pm[o] = m; g_pd[o] = den; g_pw[o] = wv;
}

__global__ void smax_comb(int head) {
    int d = threadIdx.x, b = blockIdx.x;
    float m = -1e30f, den = 0.f, wv = 0.f;
#pragma unroll
    for (int c = 0; c < 16; ++c) {
        int o = (b * 16 + c) * DD + d;
        float m2 = g_pm[o], nm = fmaxf(m, m2);
        float f = __expf(m - nm), e = __expf(m2 - nm);
        den = den * f + g_pd[o] * e;
        wv  = wv  * f + g_pw[o] * e;
        m = nm;
    }
    g_x[b * (HH * DD) + head * DD + d] = wv / den;
}

// ---------------- composition of chained projections ------------------------
__global__ void compose_mat(const float* __restrict__ Wi, const float* __restrict__ Min,
                            float* __restrict__ Mout) {
    __shared__ float row[DD];
    int d = blockIdx.x, e = threadIdx.x;
    row[e] = Wi[d * DD + e]; __syncthreads();
    float acc = 0.f;
#pragma unroll 8
    for (int c = 0; c < DD; ++c) acc += row[c] * Min[c * DD + e];
    Mout[d * DD + e] = acc;
}

__global__ void compose_bias(const float* __restrict__ Wi, const float* __restrict__ bi,
                             const float* __restrict__ cin, float* __restrict__ cout) {
    __shared__ float cp[DD];
    int d = threadIdx.x;
    cp[d] = cin[d]; __syncthreads();
    float acc = bi[d];
    for (int e = 0; e < DD; ++e) acc += Wi[d * DD + e] * cp[e];
    cout[d] = acc;
}

__global__ void sub_vec() {
    int i = blockIdx.x * blockDim.x + threadIdx.x;
    if (i < HH * DD) g_cw[i] = g_ck[i] - g_cq[i];
}

// ---------------- tiny MLP ---------------------------------------------------
__global__ void mlp_gemm(const float* __restrict__ in, int K, const float* __restrict__ W,
                         const float* __restrict__ bias, float* __restrict__ out, int dorelu) {
    __shared__ float sA[1024];
    int b = blockIdx.x, d = threadIdx.x;
    for (int i = d; i < K; i += blockDim.x) sA[i] = in[b * K + i];
    __syncthreads();
    float acc = bias[d];
    const float* w = W + (size_t)d * K;
#pragma unroll 8
    for (int c = 0; c < K; ++c) acc += sA[c] * w[c];
    if (dorelu) acc = fmaxf(acc, 0.f);
    out[b * DD + d] = acc;
}

// ---------------- launch -----------------------------------------------------
extern "C" void kernel_launch(void* const* d_in, const int* in_sizes, int n_in,
                              void* d_out, int out_size) {
    const float* q   = (const float*)d_in[0];
    const float* k   = (const float*)d_in[1];
    const float* v   = (const float*)d_in[2];
    const float* wq  = (const float*)d_in[3];
    const float* bq  = (const float*)d_in[4];
    const float* wk  = (const float*)d_in[5];
    const float* bk  = (const float*)d_in[6];
    const float* wv  = (const float*)d_in[7];
    const float* bv  = (const float*)d_in[8];
    const float* g1  = (const float*)d_in[9];
    const float* be1 = (const float*)d_in[10];
    const float* wl1 = (const float*)d_in[11];
    const float* bl1 = (const float*)d_in[12];
    const float* g2  = (const float*)d_in[13];
    const float* be2 = (const float*)d_in[14];
    const float* wl2 = (const float*)d_in[15];
    const float* bl2 = (const float*)d_in[16];
    const float* mw0 = (const float*)d_in[17];
    const float* mb0 = (const float*)d_in[18];
    const float* mw1 = (const float*)d_in[19];
    const float* mb1 = (const float*)d_in[20];
    const float* mw2 = (const float*)d_in[21];
    const float* mb2 = (const float*)d_in[22];
    float* out = (float*)d_out;

    float *Mq, *Mk, *Mv, *cq, *ck, *cv, *cw, *W, *W2, *W4, *Vi;
    float *sc1, *sh1, *sc2, *sh2, *X, *H0, *H1;
    cudaGetSymbolAddress((void**)&Mq,  g_Mq);
    cudaGetSymbolAddress((void**)&Mk,  g_Mk);
    cudaGetSymbolAddress((void**)&Mv,  g_Mv);
    cudaGetSymbolAddress((void**)&cq,  g_cq);
    cudaGetSymbolAddress((void**)&ck,  g_ck);
    cudaGetSymbolAddress((void**)&cv,  g_cv);
    cudaGetSymbolAddress((void**)&cw,  g_cw);
    cudaGetSymbolAddress((void**)&W,   g_W);
    cudaGetSymbolAddress((void**)&W2,  g_W2);
    cudaGetSymbolAddress((void**)&W4,  g_W4);
    cudaGetSymbolAddress((void**)&Vi,  g_Vi);
    cudaGetSymbolAddress((void**)&sc1, g_sc1);
    cudaGetSymbolAddress((void**)&sh1, g_sh1);
    cudaGetSymbolAddress((void**)&sc2, g_sc2);
    cudaGetSymbolAddress((void**)&sh2, g_sh2);
    cudaGetSymbolAddress((void**)&X,   g_x);
    cudaGetSymbolAddress((void**)&H0,  g_h0);
    cudaGetSymbolAddress((void**)&H1,  g_h1);

    const size_t MB = (size_t)DD * DD * sizeof(float);
    const size_t VB = (size_t)DD * sizeof(float);

    // head 0: composed matrices are just the first-layer weights/biases
    cudaMemcpyAsync(Mq, wq, MB, cudaMemcpyDeviceToDevice);
    cudaMemcpyAsync(Mk, wk, MB, cudaMemcpyDeviceToDevice);
    cudaMemcpyAsync(Mv, wv, MB, cudaMemcpyDeviceToDevice);
    cudaMemcpyAsync(cq, bq, VB, cudaMemcpyDeviceToDevice);
    cudaMemcpyAsync(ck, bk, VB, cudaMemcpyDeviceToDevice);
    cudaMemcpyAsync(cv, bv, VB, cudaMemcpyDeviceToDevice);
    for (int i = 1; i < HH; ++i) {
        int mo = i * DD * DD, vo = i * DD, po = (i - 1) * DD * DD, pv = (i - 1) * DD;
        compose_mat<<<DD, DD>>>(wq + mo, Mq + po, Mq + mo);
        compose_mat<<<DD, DD>>>(wk + mo, Mk + po, Mk + mo);
        compose_mat<<<DD, DD>>>(wv + mo, Mv + po, Mv + mo);
        compose_bias<<<1, DD>>>(wq + mo, bq + vo, cq + pv, cq + vo);
        compose_bias<<<1, DD>>>(wk + mo, bk + vo, ck + pv, ck + vo);
        compose_bias<<<1, DD>>>(wv + mo, bv + vo, cv + pv, cv + vo);
    }
    sub_vec<<<1, HH * DD>>>();

    dim3 gg(DD / 64, NN / 128);   // (4, 512)
    for (int i = 0; i < HH; ++i) {
        int mo = i * DD * DD, vo = i * DD;
        // W = k0 @ Mk^T - q0 @ Mq^T + (ck - cq)
        gemm_bf16x3<<<gg, 256>>>(k, q, Mk + mo, Mq + mo, -1.f, cw + vo,
                                 nullptr, nullptr, W, 2 * DD);
        bn_stats1<<<512, 256>>>(W);
        bn_stats2<<<DD, 256>>>(g1 + vo, be1 + vo, sc1, sh1);
        // W2 = relu(bn(W)) @ wl1^T + bl1
        gemm_bf16x3<<<gg, 256>>>(W, nullptr, wl1 + mo, nullptr, 1.f, bl1 + vo,
                                 sc1, sh1, W2, DD);
        bn_stats1<<<512, 256>>>(W2);
        bn_stats2<<<DD, 256>>>(g2 + vo, be2 + vo, sc2, sh2);
        // W4 (logits) = relu(bn(W2)) @ wl2^T + bl2
        gemm_bf16x3<<<gg, 256>>>(W2, nullptr, wl2 + mo, nullptr, 1.f, bl2 + vo,
                                 sc2, sh2, W4, DD);
        // Vi = v0 @ Mv^T + cv
        gemm_bf16x3<<<gg, 256>>>(v, nullptr, Mv + mo, nullptr, 1.f, cv + vo,
                                 nullptr, nullptr, Vi, DD);
        // softmax over S + weighted V sum -> g_x[:, i*256:(i+1)*256]
        smax_part<<<dim3(16, BB), 256>>>(W4, Vi);
        smax_comb<<<BB, 256>>>(i);
    }

    // final MLP
    mlp_gemm<<<BB, DD>>>(X,  HH * DD, mw0, mb0, H0, 1);
    mlp_gemm<<<BB, DD>>>(H0, DD,      mw1, mb1, H1, 1);
    mlp_gemm<<<BB, DD>>>(H1, DD,      mw2, mb2, out, 0);
    (void)in_sizes; (void)n_in; (void)out_size;
}

// round 4
// speedup vs baseline: 1.4021x; 1.4021x over previous
#include <cuda_runtime.h>
#include <cuda_bf16.h>
#include <math.h>

#define SQ 2048
#define BB 32
#define DD 256
#define HH 4
#define NN (SQ*BB)
#define EPSV 1e-5f
#define PITCH 40          // bf16 units per smem row (80B: conflict-free LDSM, 5r mod 8)

// ---------------- scratch --------------------------------------------------
__device__ __align__(128) float g_W [NN*DD];
__device__ __align__(128) float g_W2[NN*DD];
__device__ __align__(128) float g_W4[NN*DD];
__device__ __align__(128) float g_Vi[NN*DD];
__device__ __align__(128) float g_Mq[HH*DD*DD];
__device__ __align__(128) float g_Mk[HH*DD*DD];
__device__ __align__(128) float g_Mv[HH*DD*DD];
__device__ __align__(128) __nv_bfloat16 g_Bh[327680];
__device__ __align__(128) __nv_bfloat16 g_Bl[327680];
__device__ float g_cq[HH*DD], g_ck[HH*DD], g_cv[HH*DD], g_cw[HH*DD];
__device__ float g_ps[DD*512], g_pq2[DD*512];
__device__ float g_sc1[DD], g_sh1[DD], g_sc2[DD], g_sh2[DD];
__device__ float g_pm[BB*16*DD], g_pd[BB*16*DD], g_pw[BB*16*DD];
__device__ float g_x[BB*HH*DD];
__device__ float g_h0[BB*DD], g_h1[BB*DD];

// ---------------- helpers --------------------------------------------------
__device__ __forceinline__ unsigned split_pack(float f0, float f1, unsigned& lo) {
    __nv_bfloat16 h0 = __float2bfloat16(f0);
    __nv_bfloat16 h1 = __float2bfloat16(f1);
    __nv_bfloat16 l0 = __float2bfloat16(f0 - __bfloat162float(h0));
    __nv_bfloat16 l1 = __float2bfloat16(f1 - __bfloat162float(h1));
    __nv_bfloat162 hv = __halves2bfloat162(h0, h1);
    __nv_bfloat162 lv = __halves2bfloat162(l0, l1);
    lo = *reinterpret_cast<unsigned*>(&lv);
    return *reinterpret_cast<unsigned*>(&hv);
}

__device__ __forceinline__ void mma16816(float* c, const unsigned* a, const unsigned* b) {
    asm volatile(
        "mma.sync.aligned.m16n8k16.row.col.f32.bf16.bf16.f32 "
        "{%0,%1,%2,%3}, {%4,%5,%6,%7}, {%8,%9}, {%0,%1,%2,%3};"
        : "+f"(c[0]), "+f"(c[1]), "+f"(c[2]), "+f"(c[3])
        : "r"(a[0]), "r"(a[1]), "r"(a[2]), "r"(a[3]), "r"(b[0]), "r"(b[1]));
}

__device__ __forceinline__ void ldsm4(unsigned* r, unsigned addr) {
    asm volatile("ldmatrix.sync.aligned.m8n8.x4.shared.b16 {%0,%1,%2,%3}, [%4];"
        : "=r"(r[0]), "=r"(r[1]), "=r"(r[2]), "=r"(r[3]) : "r"(addr));
}

// ---------------- main tensor-core GEMM ------------------------------------
// C[128x64 tile] = [A0|A1](fp32, optional relu(x*sc+sh)) @ Bsplit^T + bias
// B pre-split bf16 hi/lo planes, row-major [n][k], leading dim ldb.
// STATS: fused per-rowblock channel sum/sumsq partials (deterministic).
template<bool TRANS, bool STATS>
__global__ void __launch_bounds__(256, 2)
gemm_tc(const float* __restrict__ A0, const float* __restrict__ A1,
        const __nv_bfloat16* __restrict__ Bh, const __nv_bfloat16* __restrict__ Bl,
        int ldb, const float* __restrict__ bias,
        const float* __restrict__ ascale, const float* __restrict__ ashift,
        float* __restrict__ C, float* __restrict__ ps, float* __restrict__ pq,
        int Ktot)
{
    extern __shared__ __align__(16) unsigned char smem[];
    __nv_bfloat16* asH = (__nv_bfloat16*)smem;              // 2 bufs * 128*PITCH
    __nv_bfloat16* asL = asH + 2*128*PITCH;
    __nv_bfloat16* bsH = asL + 2*128*PITCH;                 // 2 bufs * 64*PITCH
    __nv_bfloat16* bsL = bsH + 2*64*PITCH;
    const unsigned aHb = (unsigned)__cvta_generic_to_shared(asH);
    const unsigned aLb = (unsigned)__cvta_generic_to_shared(asL);
    const unsigned bHb = (unsigned)__cvta_generic_to_shared(bsH);
    const unsigned bLb = (unsigned)__cvta_generic_to_shared(bsL);

    const int tid = threadIdx.x, lane = tid & 31, warp = tid >> 5;
    const int wm = warp & 3, wn = warp >> 2;
    const int g = lane >> 2, tg = lane & 3;
    const int rowBlk = blockIdx.y * 128, colBlk = blockIdx.x * 64;

    const int ar  = tid >> 3;           // A ldg: rows ar+p*32
    const int ac4 = (tid & 7) * 4;
    const int br  = tid >> 2;           // B ldg: row 0..63
    const int bc8 = (tid & 3) * 8;

    // ldmatrix lane address components
    const int lrow = (lane & 7) + ((lane >> 3) & 1) * 8;
    const int lkof = ((lane >> 4) & 1) * 8;

    float acc[2][4][4];
#pragma unroll
    for (int a = 0; a < 2; ++a)
#pragma unroll
        for (int b = 0; b < 4; ++b)
#pragma unroll
            for (int c = 0; c < 4; ++c) acc[a][b][c] = 0.f;

    float4 Ar[4]; uint4 Brh, Brl;

    auto ldg_tile = [&](int k0) {
        const float* src = A0; int kb = k0;
        if (A1 != nullptr && k0 >= DD) { src = A1; kb = k0 - DD; }
#pragma unroll
        for (int p = 0; p < 4; ++p)
            Ar[p] = *reinterpret_cast<const float4*>(
                &src[(size_t)(rowBlk + ar + p*32) * DD + kb + ac4]);
        Brh = *reinterpret_cast<const uint4*>(&Bh[(size_t)(colBlk + br) * ldb + k0 + bc8]);
        Brl = *reinterpret_cast<const uint4*>(&Bl[(size_t)(colBlk + br) * ldb + k0 + bc8]);
    };

    auto sts_tile = [&](int buf, int k0) {
#pragma unroll
        for (int p = 0; p < 4; ++p) {
            float f[4] = {Ar[p].x, Ar[p].y, Ar[p].z, Ar[p].w};
            if (TRANS) {
#pragma unroll
                for (int j = 0; j < 4; ++j) {
                    int ch = k0 + ac4 + j;
                    f[j] = fmaxf(f[j] * ascale[ch] + ashift[ch], 0.f);
                }
            }
            unsigned l0, l1;
            unsigned h0 = split_pack(f[0], f[1], l0);
            unsigned h1 = split_pack(f[2], f[3], l1);
            int u = (buf*128 + ar + p*32) * PITCH + ac4;
            *reinterpret_cast<uint2*>(&asH[u]) = make_uint2(h0, h1);
            *reinterpret_cast<uint2*>(&asL[u]) = make_uint2(l0, l1);
        }
        int ub = (buf*64 + br) * PITCH + bc8;
        *reinterpret_cast<uint4*>(&bsH[ub]) = Brh;
        *reinterpret_cast<uint4*>(&bsL[ub]) = Brl;
    };

    auto compute = [&](int buf) {
#pragma unroll
        for (int kk = 0; kk < 2; ++kk) {
            const int kp = kk * 16;
            unsigned aH[2][4], aL[2][4], bHf[2][4], bLf[2][4];
#pragma unroll
            for (int mi = 0; mi < 2; ++mi) {
                unsigned off = ((buf*128 + wm*32 + mi*16 + lrow) * PITCH + kp + lkof) * 2;
                ldsm4(aH[mi], aHb + off);
                ldsm4(aL[mi], aLb + off);
            }
#pragma unroll
            for (int p = 0; p < 2; ++p) {
                unsigned off = ((buf*64 + wn*32 + p*16 + lrow) * PITCH + kp + lkof) * 2;
                ldsm4(bHf[p], bHb + off);
                ldsm4(bLf[p], bLb + off);
            }
#pragma unroll
            for (int mi = 0; mi < 2; ++mi)
#pragma unroll
                for (int ni = 0; ni < 4; ++ni) {
                    const int p = ni >> 1, s = ni & 1;
                    unsigned bh[2] = {bHf[p][s], bHf[p][s + 2]};
                    unsigned bl[2] = {bLf[p][s], bLf[p][s + 2]};
                    mma16816(acc[mi][ni], aH[mi], bh);
                    mma16816(acc[mi][ni], aH[mi], bl);
                    mma16816(acc[mi][ni], aL[mi], bh);
                }
        }
    };

    ldg_tile(0);
    sts_tile(0, 0);
    const int nK = Ktot >> 5;
    for (int kt = 0; kt < nK; ++kt) {
        __syncthreads();
        const bool pf = (kt + 1 < nK);
        if (pf) ldg_tile((kt + 1) * 32);
        compute(kt & 1);
        if (pf) sts_tile((kt + 1) & 1, (kt + 1) * 32);
    }

    // ---- epilogue: bias add + store + fused stats ----
#pragma unroll
    for (int ni = 0; ni < 4; ++ni) {
        int c = colBlk + wn*32 + ni*8 + tg*2;
        float b0 = bias[c], b1 = bias[c + 1];
#pragma unroll
        for (int mi = 0; mi < 2; ++mi) {
            acc[mi][ni][0] += b0; acc[mi][ni][1] += b1;
            acc[mi][ni][2] += b0; acc[mi][ni][3] += b1;
            int r = rowBlk + wm*32 + mi*16 + g;
            *reinterpret_cast<float2*>(&C[(size_t)r * DD + c]) =
                make_float2(acc[mi][ni][0], acc[mi][ni][1]);
            *reinterpret_cast<float2*>(&C[(size_t)(r + 8) * DD + c]) =
                make_float2(acc[mi][ni][2], acc[mi][ni][3]);
        }
    }
    if (STATS) {
        __syncthreads();                       // smem reuse safe
        float* sS = (float*)smem;              // [4][64]
        float* sQ = sS + 256;
#pragma unroll
        for (int ni = 0; ni < 4; ++ni)
#pragma unroll
            for (int j = 0; j < 2; ++j) {
                float v0 = acc[0][ni][j], v1 = acc[0][ni][j + 2];
                float v2 = acc[1][ni][j], v3 = acc[1][ni][j + 2];
                float s = v0 + v1 + v2 + v3;
                float q = v0*v0 + v1*v1 + v2*v2 + v3*v3;
#pragma unroll
                for (int off = 4; off < 32; off <<= 1) {
                    s += __shfl_xor_sync(0xffffffffu, s, off);
                    q += __shfl_xor_sync(0xffffffffu, q, off);
                }
                if (g == 0) {
                    int ch = wn*32 + ni*8 + tg*2 + j;
                    sS[wm*64 + ch] = s;
                    sQ[wm*64 + ch] = q;
                }
            }
        __syncthreads();
        if (tid < 64) {
            float s = sS[tid] + sS[64 + tid] + sS[128 + tid] + sS[192 + tid];
            float q = sQ[tid] + sQ[64 + tid] + sQ[128 + tid] + sQ[192 + tid];
            ps[(size_t)(colBlk + tid) * 512 + blockIdx.y] = s;
            pq[(size_t)(colBlk + tid) * 512 + blockIdx.y] = q;
        }
    }
}

// ---------------- B pre-split (per head) -----------------------------------
__global__ void conv_b(const float* __restrict__ Mk, const float* __restrict__ Mq,
                       const float* __restrict__ wl1, const float* __restrict__ wl2,
                       const float* __restrict__ Mv) {
    int gid = blockIdx.x * 256 + threadIdx.x;      // 0..327679
    float v;
    if (gid < 131072) {                            // [Mk | -Mq]  256 x 512
        int n = gid >> 9, kk = gid & 511;
        v = (kk < DD) ? Mk[n*DD + kk] : -Mq[n*DD + kk - DD];
    } else if (gid < 196608) v = wl1[gid - 131072];
    else if   (gid < 262144) v = wl2[gid - 196608];
    else                     v = Mv [gid - 262144];
    __nv_bfloat16 h = __float2bfloat16(v);
    g_Bh[gid] = h;
    g_Bl[gid] = __float2bfloat16(v - __bfloat162float(h));
}

// ---------------- BN stage-2 (partials already fused in GEMM) --------------
__global__ void bn_stats2(const float* __restrict__ gamma, const float* __restrict__ beta,
                          float* __restrict__ sc, float* __restrict__ sh) {
    int d = blockIdx.x, t = threadIdx.x;
    float s  = g_ps [d*512 + t] + g_ps [d*512 + 256 + t];
    float qq = g_pq2[d*512 + t] + g_pq2[d*512 + 256 + t];
    __shared__ float ss[256], sq[256];
    ss[t] = s; sq[t] = qq; __syncthreads();
    for (int o = 128; o > 0; o >>= 1) {
        if (t < o) { ss[t] += ss[t + o]; sq[t] += sq[t + o]; }
        __syncthreads();
    }
    if (t == 0) {
        float mean = ss[0] / (float)NN;
        float var  = sq[0] / (float)NN - mean * mean;
        float is   = rsqrtf(fmaxf(var, 0.f) + EPSV);
        float scale = gamma[d] * is;
        sc[d] = scale; sh[d] = beta[d] - mean * scale;
    }
}

// ---------------- softmax over S fused with weighted-V sum ------------------
__global__ void smax_part(const float* __restrict__ W4, const float* __restrict__ V) {
    int d = threadIdx.x, ch = blockIdx.x, b = blockIdx.y;
    size_t base = ((size_t)ch * 128 * BB + b) * DD + d;
    float m = -1e30f, den = 0.f, wv = 0.f;
#pragma unroll 2
    for (int s = 0; s < 128; ++s) {
        size_t o = base + (size_t)s * BB * DD;
        float w = W4[o], vv = V[o];
        float nm = fmaxf(m, w);
        float f = __expf(m - nm), e = __expf(w - nm);
        den = den * f + e; wv = wv * f + e * vv; m = nm;
    }
    int o = (b * 16 + ch) * DD + d;
    g_pm[o] = m; g_pd[o] = den; g_pw[o] = wv;
}

__global__ void smax_comb(int head) {
    int d = threadIdx.x, b = blockIdx.x;
    float m = -1e30f, den = 0.f, wv = 0.f;
#pragma unroll
    for (int c = 0; c < 16; ++c) {
        int o = (b * 16 + c) * DD + d;
        float m2 = g_pm[o], nm = fmaxf(m, m2);
        float f = __expf(m - nm), e = __expf(m2 - nm);
        den = den * f + g_pd[o] * e;
        wv  = wv  * f + g_pw[o] * e;
        m = nm;
    }
    g_x[b * (HH * DD) + head * DD + d] = wv / den;
}

// ---------------- composition of chained projections (batched over z) ------
__global__ void compose_mat(const float* __restrict__ wq, const float* __restrict__ wk,
                            const float* __restrict__ wv, float* __restrict__ Mq,
                            float* __restrict__ Mk, float* __restrict__ Mv, int step) {
    const float* Wb; float* Mb;
    if (blockIdx.z == 0)      { Wb = wq; Mb = Mq; }
    else if (blockIdx.z == 1) { Wb = wk; Mb = Mk; }
    else                      { Wb = wv; Mb = Mv; }
    const float* Wi  = Wb + step * DD * DD;
    const float* Min = Mb + (step - 1) * DD * DD;
    float* Mout      = Mb + step * DD * DD;
    __shared__ float row[DD];
    int d = blockIdx.x, e = threadIdx.x;
    row[e] = Wi[d * DD + e]; __syncthreads();
    float acc = 0.f;
#pragma unroll 8
    for (int c = 0; c < DD; ++c) acc += row[c] * Min[c * DD + e];
    Mout[d * DD + e] = acc;
}

__global__ void compose_bias(const float* __restrict__ wq, const float* __restrict__ wk,
                             const float* __restrict__ wv, const float* __restrict__ bq,
                             const float* __restrict__ bk, const float* __restrict__ bv,
                             float* __restrict__ cq, float* __restrict__ ck,
                             float* __restrict__ cv, int step) {
    const float* Wb; const float* bb; float* cc;
    if (blockIdx.z == 0)      { Wb = wq; bb = bq; cc = cq; }
    else if (blockIdx.z == 1) { Wb = wk; bb = bk; cc = ck; }
    else                      { Wb = wv; bb = bv; cc = cv; }
    int d = blockIdx.x, t = threadIdx.x;
    float a = Wb[step*DD*DD + d*DD + t] * cc[(step-1)*DD + t];
#pragma unroll
    for (int off = 16; off > 0; off >>= 1) a += __shfl_xor_sync(0xffffffffu, a, off);
    __shared__ float w[8];
    if ((t & 31) == 0) w[t >> 5] = a;
    __syncthreads();
    if (t == 0) {
        float s = 0.f;
#pragma unroll
        for (int i = 0; i < 8; ++i) s += w[i];
        cc[step*DD + d] = bb[step*DD + d] + s;
    }
}

__global__ void sub_vec() {
    int i = blockIdx.x * blockDim.x + threadIdx.x;
    if (i < HH * DD) g_cw[i] = g_ck[i] - g_cq[i];
}

// ---------------- tiny MLP ---------------------------------------------------
__global__ void mlp_gemm(const float* __restrict__ in, int K, const float* __restrict__ W,
                         const float* __restrict__ bias, float* __restrict__ out, int dorelu) {
    __shared__ float sA[1024];
    int b = blockIdx.x, d = threadIdx.x;
    for (int i = d; i < K; i += blockDim.x) sA[i] = in[b * K + i];
    __syncthreads();
    float acc = bias[d];
    const float* w = W + (size_t)d * K;
#pragma unroll 8
    for (int c = 0; c < K; ++c) acc += sA[c] * w[c];
    if (dorelu) acc = fmaxf(acc, 0.f);
    out[b * DD + d] = acc;
}

// ---------------- launch -----------------------------------------------------
#define SMEM_GEMM (2*(128*PITCH + 64*PITCH)*2*2)   // 61440 bytes

extern "C" void kernel_launch(void* const* d_in, const int* in_sizes, int n_in,
                              void* d_out, int out_size) {
    const float* q   = (const float*)d_in[0];
    const float* k   = (const float*)d_in[1];
    const float* v   = (const float*)d_in[2];
    const float* wq  = (const float*)d_in[3];
    const float* bq  = (const float*)d_in[4];
    const float* wk  = (const float*)d_in[5];
    const float* bk  = (const float*)d_in[6];
    const float* wv  = (const float*)d_in[7];
    const float* bv  = (const float*)d_in[8];
    const float* g1  = (const float*)d_in[9];
    const float* be1 = (const float*)d_in[10];
    const float* wl1 = (const float*)d_in[11];
    const float* bl1 = (const float*)d_in[12];
    const float* g2  = (const float*)d_in[13];
    const float* be2 = (const float*)d_in[14];
    const float* wl2 = (const float*)d_in[15];
    const float* bl2 = (const float*)d_in[16];
    const float* mw0 = (const float*)d_in[17];
    const float* mb0 = (const float*)d_in[18];
    const float* mw1 = (const float*)d_in[19];
    const float* mb1 = (const float*)d_in[20];
    const float* mw2 = (const float*)d_in[21];
    const float* mb2 = (const float*)d_in[22];
    float* out = (float*)d_out;

    float *Mq, *Mk, *Mv, *cq, *ck, *cv, *cw, *W, *W2, *W4, *Vi;
    float *sc1, *sh1, *sc2, *sh2, *X, *H0, *H1, *PS, *PQ;
    __nv_bfloat16 *Bh, *Bl;
    cudaGetSymbolAddress((void**)&Mq,  g_Mq);
    cudaGetSymbolAddress((void**)&Mk,  g_Mk);
    cudaGetSymbolAddress((void**)&Mv,  g_Mv);
    cudaGetSymbolAddress((void**)&cq,  g_cq);
    cudaGetSymbolAddress((void**)&ck,  g_ck);
    cudaGetSymbolAddress((void**)&cv,  g_cv);
    cudaGetSymbolAddress((void**)&cw,  g_cw);
    cudaGetSymbolAddress((void**)&W,   g_W);
    cudaGetSymbolAddress((void**)&W2,  g_W2);
    cudaGetSymbolAddress((void**)&W4,  g_W4);
    cudaGetSymbolAddress((void**)&Vi,  g_Vi);
    cudaGetSymbolAddress((void**)&sc1, g_sc1);
    cudaGetSymbolAddress((void**)&sh1, g_sh1);
    cudaGetSymbolAddress((void**)&sc2, g_sc2);
    cudaGetSymbolAddress((void**)&sh2, g_sh2);
    cudaGetSymbolAddress((void**)&X,   g_x);
    cudaGetSymbolAddress((void**)&H0,  g_h0);
    cudaGetSymbolAddress((void**)&H1,  g_h1);
    cudaGetSymbolAddress((void**)&PS,  g_ps);
    cudaGetSymbolAddress((void**)&PQ,  g_pq2);
    cudaGetSymbolAddress((void**)&Bh,  g_Bh);
    cudaGetSymbolAddress((void**)&Bl,  g_Bl);

    cudaFuncSetAttribute(gemm_tc<false,true>,  cudaFuncAttributeMaxDynamicSharedMemorySize, SMEM_GEMM);
    cudaFuncSetAttribute(gemm_tc<true, true>,  cudaFuncAttributeMaxDynamicSharedMemorySize, SMEM_GEMM);
    cudaFuncSetAttribute(gemm_tc<true, false>, cudaFuncAttributeMaxDynamicSharedMemorySize, SMEM_GEMM);
    cudaFuncSetAttribute(gemm_tc<false,false>, cudaFuncAttributeMaxDynamicSharedMemorySize, SMEM_GEMM);

    const size_t MB = (size_t)DD * DD * sizeof(float);
    const size_t VB = (size_t)DD * sizeof(float);

    cudaMemcpyAsync(Mq, wq, MB, cudaMemcpyDeviceToDevice);
    cudaMemcpyAsync(Mk, wk, MB, cudaMemcpyDeviceToDevice);
    cudaMemcpyAsync(Mv, wv, MB, cudaMemcpyDeviceToDevice);
    cudaMemcpyAsync(cq, bq, VB, cudaMemcpyDeviceToDevice);
    cudaMemcpyAsync(ck, bk, VB, cudaMemcpyDeviceToDevice);
    cudaMemcpyAsync(cv, bv, VB, cudaMemcpyDeviceToDevice);
    for (int i = 1; i < HH; ++i) {
        compose_mat <<<dim3(DD,1,3), DD>>>(wq, wk, wv, Mq, Mk, Mv, i);
        compose_bias<<<dim3(DD,1,3), DD>>>(wq, wk, wv, bq, bk, bv, cq, ck, cv, i);
    }
    sub_vec<<<1, HH * DD>>>();

    dim3 gg(DD / 64, NN / 128);   // (4, 512)
    for (int i = 0; i < HH; ++i) {
        int mo = i * DD * DD, vo = i * DD;
        conv_b<<<1280, 256>>>(Mk + mo, Mq + mo, wl1 + mo, wl2 + mo, Mv + mo);
        // W = k0@Mk^T - q0@Mq^T + cw   (+ fused BN1 partials)
        gemm_tc<false,true><<<gg, 256, SMEM_GEMM>>>(
            k, q, Bh, Bl, 512, cw + vo, nullptr, nullptr, W, PS, PQ, 512);
        bn_stats2<<<DD, 256>>>(g1 + vo, be1 + vo, sc1, sh1);
        // W2 = relu(bn(W)) @ wl1^T + bl1   (+ fused BN2 partials)
        gemm_tc<true,true><<<gg, 256, SMEM_GEMM>>>(
            W, nullptr, Bh + 131072, Bl + 131072, 256, bl1 + vo, sc1, sh1, W2, PS, PQ, 256);
        bn_stats2<<<DD, 256>>>(g2 + vo, be2 + vo, sc2, sh2);
        // W4 = relu(bn(W2)) @ wl2^T + bl2
        gemm_tc<true,false><<<gg, 256, SMEM_GEMM>>>(
            W2, nullptr, Bh + 196608, Bl + 196608, 256, bl2 + vo, sc2, sh2, W4, PS, PQ, 256);
        // Vi = v0 @ Mv^T + cv
        gemm_tc<false,false><<<gg, 256, SMEM_GEMM>>>(
            v, nullptr, Bh + 262144, Bl + 262144, 256, cv + vo, nullptr, nullptr, Vi, PS, PQ, 256);
        smax_part<<<dim3(16, BB), 256>>>(W4, Vi);
        smax_comb<<<BB, 256>>>(i);
    }

    mlp_gemm<<<BB, DD>>>(X,  HH * DD, mw0, mb0, H0, 1);
    mlp_gemm<<<BB, DD>>>(H0, DD,      mw1, mb1, H1, 1);
    mlp_gemm<<<BB, DD>>>(H1, DD,      mw2, mb2, out, 0);
    (void)in_sizes; (void)n_in; (void)out_size;
}